// round 9
// baseline (speedup 1.0000x reference)
#include <cuda_runtime.h>
#include <math.h>

#define NB 4
#define TT 1024
#define DD 1024
#define HH 16
#define CC 64

// scratch
__device__ float g_qkv[(size_t)NB * TT * 3 * DD];       // [N*T, 3D]
__device__ float g_q[(size_t)NB * HH * TT * CC];        // rotated q [n,h,t,c]
__device__ float g_o[(size_t)NB * TT * DD];             // [N*T, D]
__device__ unsigned g_mbits[(size_t)NB * TT * TT / 32]; // packed mask

// ---------------------------------------------------------------------------
__device__ __forceinline__ unsigned f2tf(float x) {
    unsigned r;
    asm("cvt.rna.tf32.f32 %0, %1;" : "=r"(r) : "f"(x));
    return r;
}

__device__ __forceinline__ void mma_tf32(float c[4], const unsigned a[4],
                                         const unsigned b[2]) {
    asm volatile(
        "mma.sync.aligned.m16n8k8.row.col.f32.tf32.tf32.f32 "
        "{%0,%1,%2,%3},{%4,%5,%6,%7},{%8,%9},{%0,%1,%2,%3};"
        : "+f"(c[0]), "+f"(c[1]), "+f"(c[2]), "+f"(c[3])
        : "r"(a[0]), "r"(a[1]), "r"(a[2]), "r"(a[3]), "r"(b[0]), "r"(b[1]));
}

// ---------------------------------------------------------------------------
// tf32 tensor-core GEMM (TN): C[M,N] = A[M,K] @ B[N,K]^T, fp32 accumulate.
// ---------------------------------------------------------------------------
__global__ __launch_bounds__(256) void gemm_tn_tf32(
    const float* __restrict__ A, const float* __restrict__ B,
    float* __restrict__ C, int M, int N, int K) {
    __shared__ unsigned As[128][20];
    __shared__ unsigned Bs[128][20];
    const int tid = threadIdx.x;
    const int m0 = blockIdx.y * 128, n0 = blockIdx.x * 128;
    const int warp = tid >> 5, lane = tid & 31;
    const int wm = (warp & 3) * 32, wn = (warp >> 2) * 64;
    const int g = lane >> 2, t = lane & 3;
    const int lrow = tid >> 1, lc = (tid & 1) * 8;

    float acc[2][8][4] = {};

    for (int k0 = 0; k0 < K; k0 += 16) {
        {
            const float* pa = &A[(size_t)(m0 + lrow) * K + k0 + lc];
            float4 v0 = *(const float4*)pa;
            float4 v1 = *(const float4*)(pa + 4);
            As[lrow][lc + 0] = f2tf(v0.x); As[lrow][lc + 1] = f2tf(v0.y);
            As[lrow][lc + 2] = f2tf(v0.z); As[lrow][lc + 3] = f2tf(v0.w);
            As[lrow][lc + 4] = f2tf(v1.x); As[lrow][lc + 5] = f2tf(v1.y);
            As[lrow][lc + 6] = f2tf(v1.z); As[lrow][lc + 7] = f2tf(v1.w);
            const float* pb = &B[(size_t)(n0 + lrow) * K + k0 + lc];
            float4 w0 = *(const float4*)pb;
            float4 w1 = *(const float4*)(pb + 4);
            Bs[lrow][lc + 0] = f2tf(w0.x); Bs[lrow][lc + 1] = f2tf(w0.y);
            Bs[lrow][lc + 2] = f2tf(w0.z); Bs[lrow][lc + 3] = f2tf(w0.w);
            Bs[lrow][lc + 4] = f2tf(w1.x); Bs[lrow][lc + 5] = f2tf(w1.y);
            Bs[lrow][lc + 6] = f2tf(w1.z); Bs[lrow][lc + 7] = f2tf(w1.w);
        }
        __syncthreads();
#pragma unroll
        for (int kk = 0; kk < 16; kk += 8) {
            unsigned a[2][4], b[8][2];
#pragma unroll
            for (int mi = 0; mi < 2; mi++) {
                int r = wm + mi * 16 + g;
                a[mi][0] = As[r][kk + t];
                a[mi][1] = As[r + 8][kk + t];
                a[mi][2] = As[r][kk + t + 4];
                a[mi][3] = As[r + 8][kk + t + 4];
            }
#pragma unroll
            for (int ni = 0; ni < 8; ni++) {
                int rb = wn + ni * 8 + g;
                b[ni][0] = Bs[rb][kk + t];
                b[ni][1] = Bs[rb][kk + t + 4];
            }
#pragma unroll
            for (int mi = 0; mi < 2; mi++)
#pragma unroll
                for (int ni = 0; ni < 8; ni++)
                    mma_tf32(acc[mi][ni], a[mi], b[ni]);
        }
        __syncthreads();
    }
#pragma unroll
    for (int mi = 0; mi < 2; mi++)
#pragma unroll
        for (int ni = 0; ni < 8; ni++) {
            int row = m0 + wm + mi * 16 + g;
            int col = n0 + wn + ni * 8 + 2 * t;
            float2 v01 = make_float2(acc[mi][ni][0], acc[mi][ni][1]);
            float2 v23 = make_float2(acc[mi][ni][2], acc[mi][ni][3]);
            *(float2*)&C[(size_t)row * N + col] = v01;
            *(float2*)&C[(size_t)(row + 8) * N + col] = v23;
        }
}

// ---------------------------------------------------------------------------
__global__ void pack_mask(const int* __restrict__ mask,
                          unsigned* __restrict__ bits) {
    int i = blockIdx.x * blockDim.x + threadIdx.x;
    unsigned b = __ballot_sync(0xffffffffu, mask[i] != 0);
    if ((threadIdx.x & 31) == 0) bits[i >> 5] = b;
}

// ---------------------------------------------------------------------------
// RoPE + transpose: q -> g_q [n,h,t,c]; k,v -> output buffer [n,h,t,c].
// ---------------------------------------------------------------------------
__global__ void rope_kernel(const float* __restrict__ r,
                            float* __restrict__ kout,
                            float* __restrict__ vout) {
    int idx = blockIdx.x * blockDim.x + threadIdx.x;
    const int TOT = NB * TT * HH * (CC / 2);
    if (idx >= TOT) return;
    int j = idx % (CC / 2);
    int h = (idx / (CC / 2)) % HH;
    int t = (idx / (CC / 2) / HH) % TT;
    int n = idx / (CC / 2) / HH / TT;
    size_t row = (size_t)n * TT + t;
    const float* p = &g_qkv[row * (3 * DD) + h * CC + 2 * j];
    float q0 = p[0], q1 = p[1];
    float k0 = p[DD], k1 = p[DD + 1];
    float v0 = p[2 * DD], v1 = p[2 * DD + 1];
    float ang = r[row * (CC / 2) + j];
    float cs = cosf(ang), sn = sinf(ang);
    size_t oo = ((size_t)(n * HH + h) * TT + t) * CC + 2 * j;
    g_q[oo] = q0 * cs - q1 * sn;
    g_q[oo + 1] = q0 * sn + q1 * cs;
    kout[oo] = k0 * cs - k1 * sn;
    kout[oo + 1] = k0 * sn + k1 * cs;
    vout[oo] = v0;
    vout[oo + 1] = v1;
}

// ---------------------------------------------------------------------------
// Flash attention with tf32 mma. BQ=128, BS=64, 256 threads / 8 warps.
// Warp w owns q-rows [w*16, w*16+16). P tile is warp-private.
// Smem (dynamic, stride 68 words for conflict-free fragment loads):
//   Qs[128][68] | Ks[64][68] | Vt[64][68] (c-major) | Ps[128][68]
// ---------------------------------------------------------------------------
#define AT_STRIDE 68
#define SM_QS 0
#define SM_KS (128 * AT_STRIDE)
#define SM_VT (SM_KS + 64 * AT_STRIDE)
#define SM_PS (SM_VT + 64 * AT_STRIDE)
#define AT_SMEM_WORDS (SM_PS + 128 * AT_STRIDE)

__global__ __launch_bounds__(256, 2) void attn_mma(
    const float* __restrict__ Q, const float* __restrict__ Kg,
    const float* __restrict__ Vg, const unsigned* __restrict__ mbits) {
    extern __shared__ unsigned sm[];
    unsigned* Qs = sm + SM_QS;
    unsigned* Ks = sm + SM_KS;
    unsigned* Vt = sm + SM_VT;
    unsigned* Ps = sm + SM_PS;

    const int n = blockIdx.z, h = blockIdx.y, q0 = blockIdx.x * 128;
    const int tid = threadIdx.x;
    const int warp = tid >> 5, lane = tid & 31;
    const int g = lane >> 2, t = lane & 3;
    const int wq = warp * 16;
    const size_t base = (size_t)(n * HH + h) * TT;
    const float scale = 0.125f;   // 1/sqrt(64), exact power of 2

    {   // load Q tile (scale folded into conversion)
        int qr = tid >> 1, qc = (tid & 1) * 32;
        const float* src = &Q[(base + q0 + qr) * CC + qc];
        unsigned* dst = &Qs[qr * AT_STRIDE + qc];
#pragma unroll
        for (int u = 0; u < 8; u++) {
            float4 v = ((const float4*)src)[u];
            dst[4 * u + 0] = f2tf(v.x * scale);
            dst[4 * u + 1] = f2tf(v.y * scale);
            dst[4 * u + 2] = f2tf(v.z * scale);
            dst[4 * u + 3] = f2tf(v.w * scale);
        }
    }

    float o[8][4] = {};
    float mi0 = -1e30f, mi1 = -1e30f, li0 = 0.f, li1 = 0.f;
    const int row0 = q0 + wq + g, row1 = row0 + 8;

    for (int s0 = 0; s0 < TT; s0 += 64) {
        __syncthreads();   // prior-iter smem reads done
        {   // load K row-major, V transposed (c-major)
            int kr = tid >> 2, kc = (tid & 3) * 16;
            const float* ks = &Kg[(base + s0 + kr) * CC + kc];
            const float* vs = &Vg[(base + s0 + kr) * CC + kc];
#pragma unroll
            for (int u = 0; u < 4; u++) {
                float4 a = ((const float4*)ks)[u];
                unsigned* dk = &Ks[kr * AT_STRIDE + kc + 4 * u];
                dk[0] = f2tf(a.x); dk[1] = f2tf(a.y);
                dk[2] = f2tf(a.z); dk[3] = f2tf(a.w);
                float4 b = ((const float4*)vs)[u];
                int c = kc + 4 * u;
                Vt[(c + 0) * AT_STRIDE + kr] = f2tf(b.x);
                Vt[(c + 1) * AT_STRIDE + kr] = f2tf(b.y);
                Vt[(c + 2) * AT_STRIDE + kr] = f2tf(b.z);
                Vt[(c + 3) * AT_STRIDE + kr] = f2tf(b.w);
            }
        }
        __syncthreads();

        // ---- S = (Q*scale) K^T -----------------------------------------
        float s_[8][4] = {};
#pragma unroll
        for (int kk = 0; kk < CC; kk += 8) {
            unsigned a[4];
            a[0] = Qs[(wq + g) * AT_STRIDE + kk + t];
            a[1] = Qs[(wq + g + 8) * AT_STRIDE + kk + t];
            a[2] = Qs[(wq + g) * AT_STRIDE + kk + t + 4];
            a[3] = Qs[(wq + g + 8) * AT_STRIDE + kk + t + 4];
#pragma unroll
            for (int j = 0; j < 8; j++) {
                unsigned b[2];
                b[0] = Ks[(j * 8 + g) * AT_STRIDE + kk + t];
                b[1] = Ks[(j * 8 + g) * AT_STRIDE + kk + t + 4];
                mma_tf32(s_[j], a, b);
            }
        }

        // ---- mask -------------------------------------------------------
        {
            const unsigned* mr0 =
                &mbits[((size_t)n * TT + row0) * (TT / 32) + (s0 >> 5)];
            const unsigned* mr1 =
                &mbits[((size_t)n * TT + row1) * (TT / 32) + (s0 >> 5)];
            unsigned w00 = mr0[0], w01 = mr0[1];
            unsigned w10 = mr1[0], w11 = mr1[1];
#pragma unroll
            for (int j = 0; j < 8; j++) {
                int c = j * 8 + 2 * t;
                unsigned wa0 = (c < 32) ? w00 : w01;
                unsigned wa1 = (c < 32) ? w10 : w11;
                int b0 = (wa0 >> (c & 31)) & 1, b1 = (wa0 >> ((c + 1) & 31)) & 1;
                int b2 = (wa1 >> (c & 31)) & 1, b3 = (wa1 >> ((c + 1) & 31)) & 1;
                if (!b0) s_[j][0] = -1e30f;
                if (!b1) s_[j][1] = -1e30f;
                if (!b2) s_[j][2] = -1e30f;
                if (!b3) s_[j][3] = -1e30f;
            }
        }

        // ---- online softmax (rows g and g+8, 4 lanes t share a row) ----
        float mx0 = -1e30f, mx1 = -1e30f;
#pragma unroll
        for (int j = 0; j < 8; j++) {
            mx0 = fmaxf(mx0, fmaxf(s_[j][0], s_[j][1]));
            mx1 = fmaxf(mx1, fmaxf(s_[j][2], s_[j][3]));
        }
        mx0 = fmaxf(mx0, __shfl_xor_sync(0xffffffffu, mx0, 1));
        mx0 = fmaxf(mx0, __shfl_xor_sync(0xffffffffu, mx0, 2));
        mx1 = fmaxf(mx1, __shfl_xor_sync(0xffffffffu, mx1, 1));
        mx1 = fmaxf(mx1, __shfl_xor_sync(0xffffffffu, mx1, 2));
        float mn0 = fmaxf(mi0, mx0), mn1 = fmaxf(mi1, mx1);
        float rs0 = 0.f, rs1 = 0.f;
#pragma unroll
        for (int j = 0; j < 8; j++) {
            s_[j][0] = __expf(s_[j][0] - mn0);
            s_[j][1] = __expf(s_[j][1] - mn0);
            s_[j][2] = __expf(s_[j][2] - mn1);
            s_[j][3] = __expf(s_[j][3] - mn1);
            rs0 += s_[j][0] + s_[j][1];
            rs1 += s_[j][2] + s_[j][3];
        }
        rs0 += __shfl_xor_sync(0xffffffffu, rs0, 1);
        rs0 += __shfl_xor_sync(0xffffffffu, rs0, 2);
        rs1 += __shfl_xor_sync(0xffffffffu, rs1, 1);
        rs1 += __shfl_xor_sync(0xffffffffu, rs1, 2);
        float al0 = __expf(mi0 - mn0), al1 = __expf(mi1 - mn1);
        li0 = li0 * al0 + rs0;
        li1 = li1 * al1 + rs1;
        mi0 = mn0; mi1 = mn1;
#pragma unroll
        for (int j = 0; j < 8; j++) {
            o[j][0] *= al0; o[j][1] *= al0;
            o[j][2] *= al1; o[j][3] *= al1;
        }

        // ---- P -> smem (warp-private rows) ------------------------------
#pragma unroll
        for (int j = 0; j < 8; j++) {
            int c = j * 8 + 2 * t;
            Ps[(wq + g) * AT_STRIDE + c] = f2tf(s_[j][0]);
            Ps[(wq + g) * AT_STRIDE + c + 1] = f2tf(s_[j][1]);
            Ps[(wq + g + 8) * AT_STRIDE + c] = f2tf(s_[j][2]);
            Ps[(wq + g + 8) * AT_STRIDE + c + 1] = f2tf(s_[j][3]);
        }
        __syncwarp();

        // ---- O += P V ---------------------------------------------------
#pragma unroll
        for (int kk = 0; kk < 64; kk += 8) {
            unsigned a[4];
            a[0] = Ps[(wq + g) * AT_STRIDE + kk + t];
            a[1] = Ps[(wq + g + 8) * AT_STRIDE + kk + t];
            a[2] = Ps[(wq + g) * AT_STRIDE + kk + t + 4];
            a[3] = Ps[(wq + g + 8) * AT_STRIDE + kk + t + 4];
#pragma unroll
            for (int j = 0; j < 8; j++) {
                unsigned b[2];
                b[0] = Vt[(j * 8 + g) * AT_STRIDE + kk + t];
                b[1] = Vt[(j * 8 + g) * AT_STRIDE + kk + t + 4];
                mma_tf32(o[j], a, b);
            }
        }
    }

    // epilogue: normalize, write to g_o [N,T,D]
    float inv0 = 1.f / li0, inv1 = 1.f / li1;
#pragma unroll
    for (int j = 0; j < 8; j++) {
        int c = h * CC + j * 8 + 2 * t;
        *(float2*)&g_o[((size_t)n * TT + row0) * DD + c] =
            make_float2(o[j][0] * inv0, o[j][1] * inv0);
        *(float2*)&g_o[((size_t)n * TT + row1) * DD + c] =
            make_float2(o[j][2] * inv1, o[j][3] * inv1);
    }
}

// ---------------------------------------------------------------------------
extern "C" void kernel_launch(void* const* d_in, const int* in_sizes, int n_in,
                              void* d_out, int out_size) {
    const float* x = (const float*)d_in[0];
    const float* r = (const float*)d_in[1];
    const int* mask = (const int*)d_in[2];
    const float* Wqkv = (const float*)d_in[3];
    const float* Wout = (const float*)d_in[4];

    float* out = (float*)d_out;
    float* y = out;                                    // [N,T,D]
    float* kout = out + (size_t)NB * TT * DD;          // [N,H,T,C]
    float* vout = kout + (size_t)NB * HH * TT * CC;    // [N,H,T,C]

    float *qkv_p, *o_p, *q_p;
    unsigned* mb_p;
    cudaGetSymbolAddress((void**)&qkv_p, g_qkv);
    cudaGetSymbolAddress((void**)&o_p, g_o);
    cudaGetSymbolAddress((void**)&q_p, g_q);
    cudaGetSymbolAddress((void**)&mb_p, g_mbits);

    static int attr_set = 0;
    if (!attr_set) {
        cudaFuncSetAttribute(attn_mma,
                             cudaFuncAttributeMaxDynamicSharedMemorySize,
                             AT_SMEM_WORDS * 4);
        attr_set = 1;
    }

    // 1) qkv = x @ W_qkv^T
    {
        dim3 g(3 * DD / 128, (NB * TT) / 128);
        gemm_tn_tf32<<<g, 256>>>(x, Wqkv, qkv_p, NB * TT, 3 * DD, DD);
    }
    // 2) pack mask
    pack_mask<<<(NB * TT * TT) / 256, 256>>>(mask, mb_p);
    // 3) RoPE (writes k,v outputs + g_q)
    {
        int tot = NB * TT * HH * (CC / 2);
        rope_kernel<<<(tot + 255) / 256, 256>>>(r, kout, vout);
    }
    // 4) attention -> g_o [N,T,D]
    {
        dim3 g(TT / 128, HH, NB);
        attn_mma<<<g, 256, AT_SMEM_WORDS * 4>>>(q_p, kout, vout, mb_p);
    }
    // 5) y = o @ W_out^T
    {
        dim3 g(DD / 128, (NB * TT) / 128);
        gemm_tn_tf32<<<g, 256>>>(o_p, Wout, y, NB * TT, DD, DD);
    }
}

// round 10
// speedup vs baseline: 1.0053x; 1.0053x over previous
#include <cuda_runtime.h>
#include <math.h>

#define NB 4
#define TT 1024
#define DD 1024
#define HH 16
#define CC 64

// scratch
__device__ float g_qkv[(size_t)NB * TT * 3 * DD];       // [N*T, 3D]
__device__ float g_q[(size_t)NB * HH * TT * CC];        // rotated q [n,h,t,c]
__device__ float g_o[(size_t)NB * TT * DD];             // [N*T, D]
__device__ unsigned g_mbits[(size_t)NB * TT * TT / 32]; // packed mask

// ---------------------------------------------------------------------------
__device__ __forceinline__ unsigned f2tf(float x) {
    unsigned r;
    asm("cvt.rna.tf32.f32 %0, %1;" : "=r"(r) : "f"(x));
    return r;
}

__device__ __forceinline__ void mma_tf32(float c[4], const unsigned a[4],
                                         const unsigned b[2]) {
    asm volatile(
        "mma.sync.aligned.m16n8k8.row.col.f32.tf32.tf32.f32 "
        "{%0,%1,%2,%3},{%4,%5,%6,%7},{%8,%9},{%0,%1,%2,%3};"
        : "+f"(c[0]), "+f"(c[1]), "+f"(c[2]), "+f"(c[3])
        : "r"(a[0]), "r"(a[1]), "r"(a[2]), "r"(a[3]), "r"(b[0]), "r"(b[1]));
}

// ---------------------------------------------------------------------------
// tf32 tensor-core GEMM (TN): C[M,N] = A[M,K] @ B[N,K]^T, fp32 accumulate.
// ---------------------------------------------------------------------------
__global__ __launch_bounds__(256) void gemm_tn_tf32(
    const float* __restrict__ A, const float* __restrict__ B,
    float* __restrict__ C, int M, int N, int K) {
    __shared__ unsigned As[128][20];
    __shared__ unsigned Bs[128][20];
    const int tid = threadIdx.x;
    const int m0 = blockIdx.y * 128, n0 = blockIdx.x * 128;
    const int warp = tid >> 5, lane = tid & 31;
    const int wm = (warp & 3) * 32, wn = (warp >> 2) * 64;
    const int g = lane >> 2, t = lane & 3;
    const int lrow = tid >> 1, lc = (tid & 1) * 8;

    float acc[2][8][4] = {};

    for (int k0 = 0; k0 < K; k0 += 16) {
        {
            const float* pa = &A[(size_t)(m0 + lrow) * K + k0 + lc];
            float4 v0 = *(const float4*)pa;
            float4 v1 = *(const float4*)(pa + 4);
            As[lrow][lc + 0] = f2tf(v0.x); As[lrow][lc + 1] = f2tf(v0.y);
            As[lrow][lc + 2] = f2tf(v0.z); As[lrow][lc + 3] = f2tf(v0.w);
            As[lrow][lc + 4] = f2tf(v1.x); As[lrow][lc + 5] = f2tf(v1.y);
            As[lrow][lc + 6] = f2tf(v1.z); As[lrow][lc + 7] = f2tf(v1.w);
            const float* pb = &B[(size_t)(n0 + lrow) * K + k0 + lc];
            float4 w0 = *(const float4*)pb;
            float4 w1 = *(const float4*)(pb + 4);
            Bs[lrow][lc + 0] = f2tf(w0.x); Bs[lrow][lc + 1] = f2tf(w0.y);
            Bs[lrow][lc + 2] = f2tf(w0.z); Bs[lrow][lc + 3] = f2tf(w0.w);
            Bs[lrow][lc + 4] = f2tf(w1.x); Bs[lrow][lc + 5] = f2tf(w1.y);
            Bs[lrow][lc + 6] = f2tf(w1.z); Bs[lrow][lc + 7] = f2tf(w1.w);
        }
        __syncthreads();
#pragma unroll
        for (int kk = 0; kk < 16; kk += 8) {
            unsigned a[2][4], b[8][2];
#pragma unroll
            for (int mi = 0; mi < 2; mi++) {
                int r = wm + mi * 16 + g;
                a[mi][0] = As[r][kk + t];
                a[mi][1] = As[r + 8][kk + t];
                a[mi][2] = As[r][kk + t + 4];
                a[mi][3] = As[r + 8][kk + t + 4];
            }
#pragma unroll
            for (int ni = 0; ni < 8; ni++) {
                int rb = wn + ni * 8 + g;
                b[ni][0] = Bs[rb][kk + t];
                b[ni][1] = Bs[rb][kk + t + 4];
            }
#pragma unroll
            for (int mi = 0; mi < 2; mi++)
#pragma unroll
                for (int ni = 0; ni < 8; ni++)
                    mma_tf32(acc[mi][ni], a[mi], b[ni]);
        }
        __syncthreads();
    }
#pragma unroll
    for (int mi = 0; mi < 2; mi++)
#pragma unroll
        for (int ni = 0; ni < 8; ni++) {
            int row = m0 + wm + mi * 16 + g;
            int col = n0 + wn + ni * 8 + 2 * t;
            float2 v01 = make_float2(acc[mi][ni][0], acc[mi][ni][1]);
            float2 v23 = make_float2(acc[mi][ni][2], acc[mi][ni][3]);
            *(float2*)&C[(size_t)row * N + col] = v01;
            *(float2*)&C[(size_t)(row + 8) * N + col] = v23;
        }
}

// ---------------------------------------------------------------------------
__global__ void pack_mask(const int* __restrict__ mask,
                          unsigned* __restrict__ bits) {
    int i = blockIdx.x * blockDim.x + threadIdx.x;
    unsigned b = __ballot_sync(0xffffffffu, mask[i] != 0);
    if ((threadIdx.x & 31) == 0) bits[i >> 5] = b;
}

// ---------------------------------------------------------------------------
// RoPE + transpose: q -> g_q [n,h,t,c]; k,v -> output buffer [n,h,t,c].
// ---------------------------------------------------------------------------
__global__ void rope_kernel(const float* __restrict__ r,
                            float* __restrict__ kout,
                            float* __restrict__ vout) {
    int idx = blockIdx.x * blockDim.x + threadIdx.x;
    const int TOT = NB * TT * HH * (CC / 2);
    if (idx >= TOT) return;
    int j = idx % (CC / 2);
    int h = (idx / (CC / 2)) % HH;
    int t = (idx / (CC / 2) / HH) % TT;
    int n = idx / (CC / 2) / HH / TT;
    size_t row = (size_t)n * TT + t;
    const float* p = &g_qkv[row * (3 * DD) + h * CC + 2 * j];
    float q0 = p[0], q1 = p[1];
    float k0 = p[DD], k1 = p[DD + 1];
    float v0 = p[2 * DD], v1 = p[2 * DD + 1];
    float ang = r[row * (CC / 2) + j];
    float cs = cosf(ang), sn = sinf(ang);
    size_t oo = ((size_t)(n * HH + h) * TT + t) * CC + 2 * j;
    g_q[oo] = q0 * cs - q1 * sn;
    g_q[oo + 1] = q0 * sn + q1 * cs;
    kout[oo] = k0 * cs - k1 * sn;
    kout[oo + 1] = k0 * sn + k1 * cs;
    vout[oo] = v0;
    vout[oo + 1] = v1;
}

// ---------------------------------------------------------------------------
// Flash attention with tf32 mma. BQ=128, BS=64, 256 threads / 8 warps.
// Warp w owns q-rows [w*16, w*16+16). P tile is warp-private.
// Smem (dynamic, stride 68 words for conflict-free fragment loads):
//   Qs[128][68] | Ks[64][68] | Vt[64][68] (c-major) | Ps[128][68]
// ---------------------------------------------------------------------------
#define AT_STRIDE 68
#define SM_QS 0
#define SM_KS (128 * AT_STRIDE)
#define SM_VT (SM_KS + 64 * AT_STRIDE)
#define SM_PS (SM_VT + 64 * AT_STRIDE)
#define AT_SMEM_WORDS (SM_PS + 128 * AT_STRIDE)

__global__ __launch_bounds__(256, 2) void attn_mma(
    const float* __restrict__ Q, const float* __restrict__ Kg,
    const float* __restrict__ Vg, const unsigned* __restrict__ mbits) {
    extern __shared__ unsigned sm[];
    unsigned* Qs = sm + SM_QS;
    unsigned* Ks = sm + SM_KS;
    unsigned* Vt = sm + SM_VT;
    unsigned* Ps = sm + SM_PS;

    const int n = blockIdx.z, h = blockIdx.y, q0 = blockIdx.x * 128;
    const int tid = threadIdx.x;
    const int warp = tid >> 5, lane = tid & 31;
    const int g = lane >> 2, t = lane & 3;
    const int wq = warp * 16;
    const size_t base = (size_t)(n * HH + h) * TT;
    const float scale = 0.125f;   // 1/sqrt(64), exact power of 2

    {   // load Q tile (scale folded into conversion)
        int qr = tid >> 1, qc = (tid & 1) * 32;
        const float* src = &Q[(base + q0 + qr) * CC + qc];
        unsigned* dst = &Qs[qr * AT_STRIDE + qc];
#pragma unroll
        for (int u = 0; u < 8; u++) {
            float4 v = ((const float4*)src)[u];
            dst[4 * u + 0] = f2tf(v.x * scale);
            dst[4 * u + 1] = f2tf(v.y * scale);
            dst[4 * u + 2] = f2tf(v.z * scale);
            dst[4 * u + 3] = f2tf(v.w * scale);
        }
    }

    float o[8][4] = {};
    float mi0 = -1e30f, mi1 = -1e30f, li0 = 0.f, li1 = 0.f;
    const int row0 = q0 + wq + g, row1 = row0 + 8;

    for (int s0 = 0; s0 < TT; s0 += 64) {
        __syncthreads();   // prior-iter smem reads done
        {   // load K row-major, V transposed (c-major)
            int kr = tid >> 2, kc = (tid & 3) * 16;
            const float* ks = &Kg[(base + s0 + kr) * CC + kc];
            const float* vs = &Vg[(base + s0 + kr) * CC + kc];
#pragma unroll
            for (int u = 0; u < 4; u++) {
                float4 a = ((const float4*)ks)[u];
                unsigned* dk = &Ks[kr * AT_STRIDE + kc + 4 * u];
                dk[0] = f2tf(a.x); dk[1] = f2tf(a.y);
                dk[2] = f2tf(a.z); dk[3] = f2tf(a.w);
                float4 b = ((const float4*)vs)[u];
                int c = kc + 4 * u;
                Vt[(c + 0) * AT_STRIDE + kr] = f2tf(b.x);
                Vt[(c + 1) * AT_STRIDE + kr] = f2tf(b.y);
                Vt[(c + 2) * AT_STRIDE + kr] = f2tf(b.z);
                Vt[(c + 3) * AT_STRIDE + kr] = f2tf(b.w);
            }
        }
        __syncthreads();

        // ---- S = (Q*scale) K^T -----------------------------------------
        float s_[8][4] = {};
#pragma unroll
        for (int kk = 0; kk < CC; kk += 8) {
            unsigned a[4];
            a[0] = Qs[(wq + g) * AT_STRIDE + kk + t];
            a[1] = Qs[(wq + g + 8) * AT_STRIDE + kk + t];
            a[2] = Qs[(wq + g) * AT_STRIDE + kk + t + 4];
            a[3] = Qs[(wq + g + 8) * AT_STRIDE + kk + t + 4];
#pragma unroll
            for (int j = 0; j < 8; j++) {
                unsigned b[2];
                b[0] = Ks[(j * 8 + g) * AT_STRIDE + kk + t];
                b[1] = Ks[(j * 8 + g) * AT_STRIDE + kk + t + 4];
                mma_tf32(s_[j], a, b);
            }
        }

        // ---- mask -------------------------------------------------------
        {
            const unsigned* mr0 =
                &mbits[((size_t)n * TT + row0) * (TT / 32) + (s0 >> 5)];
            const unsigned* mr1 =
                &mbits[((size_t)n * TT + row1) * (TT / 32) + (s0 >> 5)];
            unsigned w00 = mr0[0], w01 = mr0[1];
            unsigned w10 = mr1[0], w11 = mr1[1];
#pragma unroll
            for (int j = 0; j < 8; j++) {
                int c = j * 8 + 2 * t;
                unsigned wa0 = (c < 32) ? w00 : w01;
                unsigned wa1 = (c < 32) ? w10 : w11;
                int b0 = (wa0 >> (c & 31)) & 1, b1 = (wa0 >> ((c + 1) & 31)) & 1;
                int b2 = (wa1 >> (c & 31)) & 1, b3 = (wa1 >> ((c + 1) & 31)) & 1;
                if (!b0) s_[j][0] = -1e30f;
                if (!b1) s_[j][1] = -1e30f;
                if (!b2) s_[j][2] = -1e30f;
                if (!b3) s_[j][3] = -1e30f;
            }
        }

        // ---- online softmax (rows g and g+8, 4 lanes t share a row) ----
        float mx0 = -1e30f, mx1 = -1e30f;
#pragma unroll
        for (int j = 0; j < 8; j++) {
            mx0 = fmaxf(mx0, fmaxf(s_[j][0], s_[j][1]));
            mx1 = fmaxf(mx1, fmaxf(s_[j][2], s_[j][3]));
        }
        mx0 = fmaxf(mx0, __shfl_xor_sync(0xffffffffu, mx0, 1));
        mx0 = fmaxf(mx0, __shfl_xor_sync(0xffffffffu, mx0, 2));
        mx1 = fmaxf(mx1, __shfl_xor_sync(0xffffffffu, mx1, 1));
        mx1 = fmaxf(mx1, __shfl_xor_sync(0xffffffffu, mx1, 2));
        float mn0 = fmaxf(mi0, mx0), mn1 = fmaxf(mi1, mx1);
        float rs0 = 0.f, rs1 = 0.f;
#pragma unroll
        for (int j = 0; j < 8; j++) {
            s_[j][0] = __expf(s_[j][0] - mn0);
            s_[j][1] = __expf(s_[j][1] - mn0);
            s_[j][2] = __expf(s_[j][2] - mn1);
            s_[j][3] = __expf(s_[j][3] - mn1);
            rs0 += s_[j][0] + s_[j][1];
            rs1 += s_[j][2] + s_[j][3];
        }
        rs0 += __shfl_xor_sync(0xffffffffu, rs0, 1);
        rs0 += __shfl_xor_sync(0xffffffffu, rs0, 2);
        rs1 += __shfl_xor_sync(0xffffffffu, rs1, 1);
        rs1 += __shfl_xor_sync(0xffffffffu, rs1, 2);
        float al0 = __expf(mi0 - mn0), al1 = __expf(mi1 - mn1);
        li0 = li0 * al0 + rs0;
        li1 = li1 * al1 + rs1;
        mi0 = mn0; mi1 = mn1;
#pragma unroll
        for (int j = 0; j < 8; j++) {
            o[j][0] *= al0; o[j][1] *= al0;
            o[j][2] *= al1; o[j][3] *= al1;
        }

        // ---- P -> smem (warp-private rows) ------------------------------
#pragma unroll
        for (int j = 0; j < 8; j++) {
            int c = j * 8 + 2 * t;
            Ps[(wq + g) * AT_STRIDE + c] = f2tf(s_[j][0]);
            Ps[(wq + g) * AT_STRIDE + c + 1] = f2tf(s_[j][1]);
            Ps[(wq + g + 8) * AT_STRIDE + c] = f2tf(s_[j][2]);
            Ps[(wq + g + 8) * AT_STRIDE + c + 1] = f2tf(s_[j][3]);
        }
        __syncwarp();

        // ---- O += P V ---------------------------------------------------
#pragma unroll
        for (int kk = 0; kk < 64; kk += 8) {
            unsigned a[4];
            a[0] = Ps[(wq + g) * AT_STRIDE + kk + t];
            a[1] = Ps[(wq + g + 8) * AT_STRIDE + kk + t];
            a[2] = Ps[(wq + g) * AT_STRIDE + kk + t + 4];
            a[3] = Ps[(wq + g + 8) * AT_STRIDE + kk + t + 4];
#pragma unroll
            for (int j = 0; j < 8; j++) {
                unsigned b[2];
                b[0] = Vt[(j * 8 + g) * AT_STRIDE + kk + t];
                b[1] = Vt[(j * 8 + g) * AT_STRIDE + kk + t + 4];
                mma_tf32(o[j], a, b);
            }
        }
    }

    // epilogue: normalize, write to g_o [N,T,D]
    float inv0 = 1.f / li0, inv1 = 1.f / li1;
#pragma unroll
    for (int j = 0; j < 8; j++) {
        int c = h * CC + j * 8 + 2 * t;
        *(float2*)&g_o[((size_t)n * TT + row0) * DD + c] =
            make_float2(o[j][0] * inv0, o[j][1] * inv0);
        *(float2*)&g_o[((size_t)n * TT + row1) * DD + c] =
            make_float2(o[j][2] * inv1, o[j][3] * inv1);
    }
}

// ---------------------------------------------------------------------------
extern "C" void kernel_launch(void* const* d_in, const int* in_sizes, int n_in,
                              void* d_out, int out_size) {
    const float* x = (const float*)d_in[0];
    const float* r = (const float*)d_in[1];
    const int* mask = (const int*)d_in[2];
    const float* Wqkv = (const float*)d_in[3];
    const float* Wout = (const float*)d_in[4];

    float* out = (float*)d_out;
    float* y = out;                                    // [N,T,D]
    float* kout = out + (size_t)NB * TT * DD;          // [N,H,T,C]
    float* vout = kout + (size_t)NB * HH * TT * CC;    // [N,H,T,C]

    float *qkv_p, *o_p, *q_p;
    unsigned* mb_p;
    cudaGetSymbolAddress((void**)&qkv_p, g_qkv);
    cudaGetSymbolAddress((void**)&o_p, g_o);
    cudaGetSymbolAddress((void**)&q_p, g_q);
    cudaGetSymbolAddress((void**)&mb_p, g_mbits);

    static int attr_set = 0;
    if (!attr_set) {
        cudaFuncSetAttribute(attn_mma,
                             cudaFuncAttributeMaxDynamicSharedMemorySize,
                             AT_SMEM_WORDS * 4);
        attr_set = 1;
    }

    // 1) qkv = x @ W_qkv^T
    {
        dim3 g(3 * DD / 128, (NB * TT) / 128);
        gemm_tn_tf32<<<g, 256>>>(x, Wqkv, qkv_p, NB * TT, 3 * DD, DD);
    }
    // 2) pack mask
    pack_mask<<<(NB * TT * TT) / 256, 256>>>(mask, mb_p);
    // 3) RoPE (writes k,v outputs + g_q)
    {
        int tot = NB * TT * HH * (CC / 2);
        rope_kernel<<<(tot + 255) / 256, 256>>>(r, kout, vout);
    }
    // 4) attention -> g_o [N,T,D]
    {
        dim3 g(TT / 128, HH, NB);
        attn_mma<<<g, 256, AT_SMEM_WORDS * 4>>>(q_p, kout, vout, mb_p);
    }
    // 5) y = o @ W_out^T
    {
        dim3 g(DD / 128, (NB * TT) / 128);
        gemm_tn_tf32<<<g, 256>>>(o_p, Wout, y, NB * TT, DD, DD);
    }
}